// round 11
// baseline (speedup 1.0000x reference)
#include <cuda_runtime.h>

// Problem constants (fixed by reference setup_inputs)
#define C_    128
#define D_    24
#define H_    128
#define W_    128
#define HW_   (H_ * W_)
#define DHW_  (D_ * HW_)
#define OUTH  7
#define OUTD  4
#define SN_   2
#define NBINS (OUTD * OUTH * OUTH)   // 196
#define CG    16                     // channels per block (gridDim.y = 8)
#define TPB   224                    // 7 warps; warp index = bin-row h (R5 structure)

#define SCALE_XY 0.125f
#define SCALE_Z  0.25f

// R5 structure (proven 172.8us) with the 16 warp-uniform wzy weights moved
// from per-thread registers to shared memory. This shrinks the NATURAL
// register allocation (no launch_bounds ceiling pressure — R2/R6/R9/R10
// law), letting the RF hold 4 CTAs x 7 warps = 28 resident warps vs 21.
__global__ __launch_bounds__(TPB)
void roialign3d_kernel(const float* __restrict__ feat,
                       const float* __restrict__ rois,
                       float* __restrict__ out,
                       int R)
{
    __shared__ float s_wzy[7][16];       // per-warp weight slab

    const int r    = blockIdx.x;         // roi
    const int cg   = blockIdx.y;         // channel group
    const int h    = threadIdx.x >> 5;   // warp id = output h (0..6)
    const int lane = threadIdx.x & 31;
    // lane -> (w bin, x tap). 28 active lanes; lanes 28..31 mirror w=6 (weight 0).
    const int  wbin   = (lane >> 2) < OUTH ? (lane >> 2) : (OUTH - 1);
    const int  tap    = lane & 3;        // (sample = tap>>1, corner = tap&1)
    const bool active = (lane >> 2) < OUTH;

    // ---- ROI params (uniform) ----
    const float* roi = rois + (size_t)r * 7;
    const int   b  = (int)__ldg(roi + 0);
    const float x1 = __ldg(roi + 1) * SCALE_XY;
    const float y1 = __ldg(roi + 2) * SCALE_XY;
    const float x2 = __ldg(roi + 3) * SCALE_XY;
    const float y2 = __ldg(roi + 4) * SCALE_XY;
    const float z1 = __ldg(roi + 5) * SCALE_Z;
    const float z2 = __ldg(roi + 6) * SCALE_Z;

    const float bw = fmaxf(x2 - x1, 1.0f) * (1.0f / OUTH);
    const float bh = fmaxf(y2 - y1, 1.0f) * (1.0f / OUTH);
    const float bd = fmaxf(z2 - z1, 1.0f) * (1.0f / OUTD);

    // ---- This lane's x tap: offset (clipped in-bounds) + weight (validity folded) ----
    int   xoff;
    float xw;
    {
        const int   s  = tap >> 1;
        float c  = x1 + ((float)wbin + 0.25f + 0.5f * (float)s) * bw;
        float v  = (c > -1.0f && c < (float)W_) ? 1.0f : 0.0f;
        float cc = fminf(fmaxf(c, 0.0f), (float)(W_ - 1));
        int   lo = (int)cc;
        int   hi = (lo < W_ - 1) ? lo + 1 : lo;
        float f  = cc - (float)lo;
        xoff = (tap & 1) ? hi : lo;
        xw   = ((tap & 1) ? f : (1.0f - f)) * v;
        if (!active) xw = 0.0f;
    }

    // ---- 4 y tap offsets for this warp's h (weights go to smem later) ----
    int yoff[4];
#pragma unroll
    for (int s = 0; s < SN_; s++) {
        float c  = y1 + ((float)h + 0.25f + 0.5f * (float)s) * bh;
        float cc = fminf(fmaxf(c, 0.0f), (float)(H_ - 1));
        int   lo = (int)cc;
        int   hi = (lo < H_ - 1) ? lo + 1 : lo;
        yoff[2*s]   = lo * W_;
        yoff[2*s+1] = hi * W_;
    }

    const int c0 = cg * CG;
    const float* pbase = feat + ((size_t)b * C_ + c0) * (size_t)DHW_ + xoff;
    float* obase = out + ((size_t)(r * C_ + c0)) * (size_t)NBINS + h * OUTH + wbin;

    const volatile float* vw = s_wzy[h];  // volatile: keep the 16 LDS reads
                                          // interleaved in the FMA tree
                                          // (short live ranges, no re-reg)

    // ---- Loop over d bin-rows ----
    for (int d = 0; d < OUTD; d++) {
        // 4 z tap offsets
        int zoff[4];
#pragma unroll
        for (int s = 0; s < SN_; s++) {
            float c  = z1 + ((float)d + 0.25f + 0.5f * (float)s) * bd;
            float cc = fminf(fmaxf(c, 0.0f), (float)(D_ - 1));
            int   lo = (int)cc;
            int   hi = (lo < D_ - 1) ? lo + 1 : lo;
            zoff[2*s]   = lo * HW_;
            zoff[2*s+1] = hi * HW_;
        }

        // 16 row offsets (address operands — stay in regs)
        int rowoff[16];
#pragma unroll
        for (int zt = 0; zt < 4; zt++)
#pragma unroll
            for (int yt = 0; yt < 4; yt++)
                rowoff[zt * 4 + yt] = zoff[zt] + yoff[yt];

        // ---- Weights: lanes 0..15 each compute ONE scalar wzy -> smem ----
        __syncwarp();
        if (lane < 16) {
            const int zt = lane >> 2;            // z tap index (0..3)
            const int yt = lane & 3;             // y tap index (0..3)
            // z tap: sample zt>>1, corner zt&1
            float cz = z1 + ((float)d + 0.25f + 0.5f * (float)(zt >> 1)) * bd;
            float vz = (cz > -1.0f && cz < (float)D_) ? 1.0f : 0.0f;
            float cc = fminf(fmaxf(cz, 0.0f), (float)(D_ - 1));
            float fz = cc - (float)((int)cc);
            float wz = ((zt & 1) ? fz : (1.0f - fz)) * vz;
            // y tap: sample yt>>1, corner yt&1
            float cy = y1 + ((float)h + 0.25f + 0.5f * (float)(yt >> 1)) * bh;
            float vy = (cy > -1.0f && cy < (float)H_) ? 1.0f : 0.0f;
            float cy2 = fminf(fmaxf(cy, 0.0f), (float)(H_ - 1));
            float fy = cy2 - (float)((int)cy2);
            float wy = ((yt & 1) ? fy : (1.0f - fy)) * vy;
            s_wzy[h][lane] = wz * wy;
        }
        __syncwarp();

        float* od = obase + (size_t)d * (OUTH * OUTH);

        // ---- Channel loop, 2 channels at a time (32 independent LDGs) ----
        for (int ci = 0; ci < CG; ci += 2) {
            const float* pA = pbase + (size_t)ci * DHW_;
            const float* pB = pA + DHW_;

            float vA[16], vB[16];
#pragma unroll
            for (int i = 0; i < 16; i++) {
                vA[i] = __ldg(pA + rowoff[i]);
                vB[i] = __ldg(pB + rowoff[i]);
            }

            // weights streamed from smem (broadcast LDS), 4 partial chains
            float a0 = 0.f, a1 = 0.f, b0 = 0.f, b1 = 0.f;
#pragma unroll
            for (int i = 0; i < 16; i += 2) {
                float w0 = vw[i];
                float w1 = vw[i + 1];
                a0 = fmaf(w0, vA[i],     a0);
                b0 = fmaf(w0, vB[i],     b0);
                a1 = fmaf(w1, vA[i + 1], a1);
                b1 = fmaf(w1, vB[i + 1], b1);
            }
            float accA = (a0 + a1) * xw;
            float accB = (b0 + b1) * xw;

            // reduce across the 4 x-taps (lanes 4w..4w+3)
            accA += __shfl_xor_sync(0xFFFFFFFFu, accA, 1);
            accA += __shfl_xor_sync(0xFFFFFFFFu, accA, 2);
            accB += __shfl_xor_sync(0xFFFFFFFFu, accB, 1);
            accB += __shfl_xor_sync(0xFFFFFFFFu, accB, 2);

            if (active && tap == 0) {
                od[(size_t)ci * NBINS]       = accA * 0.125f;  // mean over 8 samples
                od[(size_t)(ci + 1) * NBINS] = accB * 0.125f;
            }
        }
    }
}

extern "C" void kernel_launch(void* const* d_in, const int* in_sizes, int n_in,
                              void* d_out, int out_size)
{
    const float* feat = (const float*)d_in[0];
    const float* rois = (const float*)d_in[1];
    float* out = (float*)d_out;

    const int R = in_sizes[1] / 7;   // 256

    dim3 grid(R, C_ / CG, 1);        // 256 x 8 = 2048 blocks
    dim3 block(TPB, 1, 1);           // 224 threads (7 warps)
    roialign3d_kernel<<<grid, block>>>(feat, rois, out, R);
}

// round 12
// speedup vs baseline: 2.0739x; 2.0739x over previous
#include <cuda_runtime.h>

// Problem constants (fixed by reference setup_inputs)
#define C_    128
#define D_    24
#define H_    128
#define W_    128
#define HW_   (H_ * W_)
#define DHW_  (D_ * HW_)
#define OUTH  7
#define OUTD  4
#define SN_   2
#define NBINS (OUTD * OUTH * OUTH)   // 196
#define CG    16                     // channels per block (gridDim.y = 8)
#define TPB   224                    // 7 warps; warp index = bin-row h
#define NPAIR (CG / 2)               // 8 channel pairs per (d) row

#define SCALE_XY 0.125f
#define SCALE_Z  0.25f

// R5 structure (proven 172.8us) + explicit 2-stage software pipeline over the
// channel-pair loop: loads for pair j+1 are issued before the FMA tree of
// pair j, removing the tail-load wait at every iteration boundary. Natural
// register allocation rises to ~120 (two 32-value buffers) — intentionally,
// with NO launch_bounds pressure (R2/R6/R9/R11 law). 2 CTAs/SM = 14 warps,
// each with a continuously-fed load pipeline.
__global__ __launch_bounds__(TPB)
void roialign3d_kernel(const float* __restrict__ feat,
                       const float* __restrict__ rois,
                       float* __restrict__ out,
                       int R)
{
    const int r    = blockIdx.x;         // roi
    const int cg   = blockIdx.y;         // channel group
    const int h    = threadIdx.x >> 5;   // warp id = output h (0..6)
    const int lane = threadIdx.x & 31;
    // lane -> (w bin, x tap). 28 active lanes; lanes 28..31 mirror w=6 (weight 0).
    const int  wbin   = (lane >> 2) < OUTH ? (lane >> 2) : (OUTH - 1);
    const int  tap    = lane & 3;        // (sample = tap>>1, corner = tap&1)
    const bool active = (lane >> 2) < OUTH;

    // ---- ROI params (uniform) ----
    const float* roi = rois + (size_t)r * 7;
    const int   b  = (int)__ldg(roi + 0);
    const float x1 = __ldg(roi + 1) * SCALE_XY;
    const float y1 = __ldg(roi + 2) * SCALE_XY;
    const float x2 = __ldg(roi + 3) * SCALE_XY;
    const float y2 = __ldg(roi + 4) * SCALE_XY;
    const float z1 = __ldg(roi + 5) * SCALE_Z;
    const float z2 = __ldg(roi + 6) * SCALE_Z;

    const float bw = fmaxf(x2 - x1, 1.0f) * (1.0f / OUTH);
    const float bh = fmaxf(y2 - y1, 1.0f) * (1.0f / OUTH);
    const float bd = fmaxf(z2 - z1, 1.0f) * (1.0f / OUTD);

    // ---- This lane's x tap: offset (clipped in-bounds) + weight (validity folded) ----
    int   xoff;
    float xw;
    {
        const int   s  = tap >> 1;
        float c  = x1 + ((float)wbin + 0.25f + 0.5f * (float)s) * bw;
        float v  = (c > -1.0f && c < (float)W_) ? 1.0f : 0.0f;
        float cc = fminf(fmaxf(c, 0.0f), (float)(W_ - 1));
        int   lo = (int)cc;
        int   hi = (lo < W_ - 1) ? lo + 1 : lo;
        float f  = cc - (float)lo;
        xoff = (tap & 1) ? hi : lo;
        xw   = ((tap & 1) ? f : (1.0f - f)) * v;
        if (!active) xw = 0.0f;
    }

    // ---- 4 y taps for this warp's h (uniform across warp) ----
    int   yoff[4];
    float yw[4];
#pragma unroll
    for (int s = 0; s < SN_; s++) {
        float c  = y1 + ((float)h + 0.25f + 0.5f * (float)s) * bh;
        float v  = (c > -1.0f && c < (float)H_) ? 1.0f : 0.0f;
        float cc = fminf(fmaxf(c, 0.0f), (float)(H_ - 1));
        int   lo = (int)cc;
        int   hi = (lo < H_ - 1) ? lo + 1 : lo;
        float f  = cc - (float)lo;
        yoff[2*s]   = lo * W_;  yw[2*s]   = (1.0f - f) * v;
        yoff[2*s+1] = hi * W_;  yw[2*s+1] = f * v;
    }

    const int c0 = cg * CG;
    const float* pbase = feat + ((size_t)b * C_ + c0) * (size_t)DHW_ + xoff;
    float* obase = out + ((size_t)(r * C_ + c0)) * (size_t)NBINS + h * OUTH + wbin;

    // ---- Loop over d bin-rows ----
    for (int d = 0; d < OUTD; d++) {
        // 4 z taps
        int   zoff[4];
        float zw[4];
#pragma unroll
        for (int s = 0; s < SN_; s++) {
            float c  = z1 + ((float)d + 0.25f + 0.5f * (float)s) * bd;
            float v  = (c > -1.0f && c < (float)D_) ? 1.0f : 0.0f;
            float cc = fminf(fmaxf(c, 0.0f), (float)(D_ - 1));
            int   lo = (int)cc;
            int   hi = (lo < D_ - 1) ? lo + 1 : lo;
            float f  = cc - (float)lo;
            zoff[2*s]   = lo * HW_;  zw[2*s]   = (1.0f - f) * v;
            zoff[2*s+1] = hi * HW_;  zw[2*s+1] = f * v;
        }

        // 16 row offsets + scalar weights (uniform across warp)
        int   rowoff[16];
        float wzy[16];
#pragma unroll
        for (int zt = 0; zt < 4; zt++)
#pragma unroll
            for (int yt = 0; yt < 4; yt++) {
                rowoff[zt * 4 + yt] = zoff[zt] + yoff[yt];
                wzy[zt * 4 + yt]    = zw[zt] * yw[yt];
            }

        float* od = obase + (size_t)d * (OUTH * OUTH);

        // ---- Software-pipelined channel-pair loop (ping-pong buffers) ----
        float vA0[16], vB0[16], vA1[16], vB1[16];

        // prologue: load pair 0 into buffer 0
        {
            const float* pA = pbase;
            const float* pB = pA + DHW_;
#pragma unroll
            for (int i = 0; i < 16; i++) {
                vA0[i] = __ldg(pA + rowoff[i]);
                vB0[i] = __ldg(pB + rowoff[i]);
            }
        }

#pragma unroll
        for (int j = 0; j < NPAIR; j++) {
            // prefetch pair j+1 into the other buffer (static under unroll)
            if (j + 1 < NPAIR) {
                const float* pA = pbase + (size_t)((j + 1) * 2) * DHW_;
                const float* pB = pA + DHW_;
                if (j & 1) {
#pragma unroll
                    for (int i = 0; i < 16; i++) {
                        vA0[i] = __ldg(pA + rowoff[i]);
                        vB0[i] = __ldg(pB + rowoff[i]);
                    }
                } else {
#pragma unroll
                    for (int i = 0; i < 16; i++) {
                        vA1[i] = __ldg(pA + rowoff[i]);
                        vB1[i] = __ldg(pB + rowoff[i]);
                    }
                }
            }

            // compute from current buffer
            const float* vA = (j & 1) ? vA1 : vA0;
            const float* vB = (j & 1) ? vB1 : vB0;

            float a0 = 0.f, a1 = 0.f, b0 = 0.f, b1 = 0.f;
#pragma unroll
            for (int i = 0; i < 16; i += 2) {
                a0 = fmaf(wzy[i],     vA[i],     a0);
                a1 = fmaf(wzy[i + 1], vA[i + 1], a1);
                b0 = fmaf(wzy[i],     vB[i],     b0);
                b1 = fmaf(wzy[i + 1], vB[i + 1], b1);
            }
            float accA = (a0 + a1) * xw;
            float accB = (b0 + b1) * xw;

            // reduce across the 4 x-taps (lanes 4w..4w+3)
            accA += __shfl_xor_sync(0xFFFFFFFFu, accA, 1);
            accA += __shfl_xor_sync(0xFFFFFFFFu, accA, 2);
            accB += __shfl_xor_sync(0xFFFFFFFFu, accB, 1);
            accB += __shfl_xor_sync(0xFFFFFFFFu, accB, 2);

            if (active && tap == 0) {
                od[(size_t)(j * 2) * NBINS]     = accA * 0.125f;  // mean over 8
                od[(size_t)(j * 2 + 1) * NBINS] = accB * 0.125f;
            }
        }
    }
}

extern "C" void kernel_launch(void* const* d_in, const int* in_sizes, int n_in,
                              void* d_out, int out_size)
{
    const float* feat = (const float*)d_in[0];
    const float* rois = (const float*)d_in[1];
    float* out = (float*)d_out;

    const int R = in_sizes[1] / 7;   // 256

    dim3 grid(R, C_ / CG, 1);        // 256 x 8 = 2048 blocks
    dim3 block(TPB, 1, 1);           // 224 threads (7 warps)
    roialign3d_kernel<<<grid, block>>>(feat, rois, out, R);
}

// round 13
// speedup vs baseline: 2.5278x; 1.2189x over previous
#include <cuda_runtime.h>

// Problem constants (fixed by reference setup_inputs)
#define C_    128
#define D_    24
#define H_    128
#define W_    128
#define HW_   (H_ * W_)
#define DHW_  (D_ * HW_)
#define OUTH  7
#define OUTD  4
#define SN_   2
#define NBINS (OUTD * OUTH * OUTH)   // 196 bins per channel
#define CG    16                     // channels per block (gridDim.y = 8)
#define TPB   224                    // 7 warps; warp index = bin-row h
#define OUTBLK (CG * NBINS)          // 3136 floats: block's contiguous out span

#define SCALE_XY 0.125f
#define SCALE_Z  0.25f

// R5 structure (proven 172.8us) + shared-memory output staging.
// R5's scattered epilogue stores (7 lanes strided by 784B -> 7 wavefronts
// per STG, ~6.4M wavefronts chip-wide, ~28% of all L1 work) are replaced by
// conflict-free STS during compute and ONE fully-coalesced copy-out at block
// end (the block's output is a single contiguous 3136-float span).
__global__ __launch_bounds__(TPB, 3)
void roialign3d_kernel(const float* __restrict__ feat,
                       const float* __restrict__ rois,
                       float* __restrict__ out,
                       int R)
{
    __shared__ float s_out[OUTBLK];      // [ch_local][d][h][w] = out layout

    const int r    = blockIdx.x;         // roi
    const int cg   = blockIdx.y;         // channel group
    const int tid  = threadIdx.x;
    const int h    = tid >> 5;           // warp id = output h (0..6)
    const int lane = tid & 31;
    // lane -> (w bin, x tap). 28 active lanes; lanes 28..31 mirror w=6 (weight 0).
    const int  wbin   = (lane >> 2) < OUTH ? (lane >> 2) : (OUTH - 1);
    const int  tap    = lane & 3;        // (sample = tap>>1, corner = tap&1)
    const bool active = (lane >> 2) < OUTH;

    // ---- ROI params (uniform) ----
    const float* roi = rois + (size_t)r * 7;
    const int   b  = (int)__ldg(roi + 0);
    const float x1 = __ldg(roi + 1) * SCALE_XY;
    const float y1 = __ldg(roi + 2) * SCALE_XY;
    const float x2 = __ldg(roi + 3) * SCALE_XY;
    const float y2 = __ldg(roi + 4) * SCALE_XY;
    const float z1 = __ldg(roi + 5) * SCALE_Z;
    const float z2 = __ldg(roi + 6) * SCALE_Z;

    const float bw = fmaxf(x2 - x1, 1.0f) * (1.0f / OUTH);
    const float bh = fmaxf(y2 - y1, 1.0f) * (1.0f / OUTH);
    const float bd = fmaxf(z2 - z1, 1.0f) * (1.0f / OUTD);

    // ---- This lane's x tap: offset (clipped in-bounds) + weight (validity folded) ----
    int   xoff;
    float xw;
    {
        const int   s  = tap >> 1;
        float c  = x1 + ((float)wbin + 0.25f + 0.5f * (float)s) * bw;
        float v  = (c > -1.0f && c < (float)W_) ? 1.0f : 0.0f;
        float cc = fminf(fmaxf(c, 0.0f), (float)(W_ - 1));
        int   lo = (int)cc;
        int   hi = (lo < W_ - 1) ? lo + 1 : lo;
        float f  = cc - (float)lo;
        xoff = (tap & 1) ? hi : lo;
        xw   = ((tap & 1) ? f : (1.0f - f)) * v;
        if (!active) xw = 0.0f;
    }

    // ---- 4 y taps for this warp's h (uniform across warp) ----
    int   yoff[4];
    float yw[4];
#pragma unroll
    for (int s = 0; s < SN_; s++) {
        float c  = y1 + ((float)h + 0.25f + 0.5f * (float)s) * bh;
        float v  = (c > -1.0f && c < (float)H_) ? 1.0f : 0.0f;
        float cc = fminf(fmaxf(c, 0.0f), (float)(H_ - 1));
        int   lo = (int)cc;
        int   hi = (lo < H_ - 1) ? lo + 1 : lo;
        float f  = cc - (float)lo;
        yoff[2*s]   = lo * W_;  yw[2*s]   = (1.0f - f) * v;
        yoff[2*s+1] = hi * W_;  yw[2*s+1] = f * v;
    }

    const int c0 = cg * CG;
    const float* pbase = feat + ((size_t)b * C_ + c0) * (size_t)DHW_ + xoff;

    // ---- Loop over d bin-rows ----
    for (int d = 0; d < OUTD; d++) {
        // 4 z taps
        int   zoff[4];
        float zw[4];
#pragma unroll
        for (int s = 0; s < SN_; s++) {
            float c  = z1 + ((float)d + 0.25f + 0.5f * (float)s) * bd;
            float v  = (c > -1.0f && c < (float)D_) ? 1.0f : 0.0f;
            float cc = fminf(fmaxf(c, 0.0f), (float)(D_ - 1));
            int   lo = (int)cc;
            int   hi = (lo < D_ - 1) ? lo + 1 : lo;
            float f  = cc - (float)lo;
            zoff[2*s]   = lo * HW_;  zw[2*s]   = (1.0f - f) * v;
            zoff[2*s+1] = hi * HW_;  zw[2*s+1] = f * v;
        }

        // 16 row offsets + scalar weights (uniform across warp)
        int   rowoff[16];
        float wzy[16];
#pragma unroll
        for (int zt = 0; zt < 4; zt++)
#pragma unroll
            for (int yt = 0; yt < 4; yt++) {
                rowoff[zt * 4 + yt] = zoff[zt] + yoff[yt];
                wzy[zt * 4 + yt]    = zw[zt] * yw[yt];
            }

        float* sd = s_out + d * (OUTH * OUTH) + h * OUTH + wbin;

        // ---- Channel loop, 2 channels at a time (32 independent LDGs) ----
        for (int ci = 0; ci < CG; ci += 2) {
            const float* pA = pbase + (size_t)ci * DHW_;
            const float* pB = pA + DHW_;

            float vA[16], vB[16];
#pragma unroll
            for (int i = 0; i < 16; i++) {
                vA[i] = __ldg(pA + rowoff[i]);
                vB[i] = __ldg(pB + rowoff[i]);
            }

            // two partial chains each to shorten the FMA dependency
            float a0 = 0.f, a1 = 0.f, b0 = 0.f, b1 = 0.f;
#pragma unroll
            for (int i = 0; i < 16; i += 2) {
                a0 = fmaf(wzy[i],     vA[i],     a0);
                a1 = fmaf(wzy[i + 1], vA[i + 1], a1);
                b0 = fmaf(wzy[i],     vB[i],     b0);
                b1 = fmaf(wzy[i + 1], vB[i + 1], b1);
            }
            float accA = (a0 + a1) * xw;
            float accB = (b0 + b1) * xw;

            // reduce across the 4 x-taps (lanes 4w..4w+3)
            accA += __shfl_xor_sync(0xFFFFFFFFu, accA, 1);
            accA += __shfl_xor_sync(0xFFFFFFFFu, accA, 2);
            accB += __shfl_xor_sync(0xFFFFFFFFu, accB, 1);
            accB += __shfl_xor_sync(0xFFFFFFFFu, accB, 2);

            // stage to smem: 7 consecutive floats per store -> conflict-free
            if (active && tap == 0) {
                sd[ci * NBINS]       = accA * 0.125f;  // mean over 8 samples
                sd[(ci + 1) * NBINS] = accB * 0.125f;
            }
        }
    }

    // ---- Coalesced copy-out: block output is one contiguous 3136-float span ----
    __syncthreads();
    float* oblk = out + (size_t)(r * C_ + c0) * (size_t)NBINS;
#pragma unroll
    for (int i = tid; i < OUTBLK; i += TPB)
        oblk[i] = s_out[i];
}

extern "C" void kernel_launch(void* const* d_in, const int* in_sizes, int n_in,
                              void* d_out, int out_size)
{
    const float* feat = (const float*)d_in[0];
    const float* rois = (const float*)d_in[1];
    float* out = (float*)d_out;

    const int R = in_sizes[1] / 7;   // 256

    dim3 grid(R, C_ / CG, 1);        // 256 x 8 = 2048 blocks
    dim3 block(TPB, 1, 1);           // 224 threads (7 warps)
    roialign3d_kernel<<<grid, block>>>(feat, rois, out, R);
}